// round 7
// baseline (speedup 1.0000x reference)
#include <cuda_runtime.h>
#include <cstdint>

#define NA 76725
#define NA_R 76728               // padded row stride (multiple of 8) for float4 stores
#define NC 80
#define CA (NA * NC)             // 6,138,000
#define MAXK 200
#define CAND 2048
#define NT 512
#define GRID 296
#define N4 ((7 * CA) / 4)        // 10,741,500 float4 in out buffer
#define B4 32768                 // float4 per fill batch (512 KB)
#define NBATCH ((N4 + B4 - 1) / B4)   // 328
#define LO4 (CA / 4)             // label region start (float4 units)
#define HI4 ((2 * CA) / 4)
#define FULLMASK 0xFFFFFFFFu
#define NTILE ((NA + 31) / 32)   // 2398
#define NA_PAD (((NA + NT - 1) / NT) * NT)

// -------- device scratch (no allocations allowed) --------
__device__ float g_boxes[NA * 4];
__device__ float g_areas[NA];
__device__ float g_scoresT[(size_t)NC * NA_R];
__device__ int g_next;
__device__ int g_done;

// ============ kernel 1: reset counters + decode + transpose ============
__global__ void __launch_bounds__(256) k_pre(const float* __restrict__ cls,
                                             const float4* __restrict__ reg,
                                             const float4* __restrict__ anc) {
    __shared__ float tile[80 * 36];   // [class][anchor-in-tile], pad 36 (16B-aligned rows)
    const int tid = threadIdx.x;
    if (blockIdx.x == 0 && tid == 0) { g_next = 0; g_done = 0; }

    // decode
    int gid = blockIdx.x * 256 + tid;
    if (gid < NA) {
        float4 a = anc[gid];
        float4 r = reg[gid];
        float aw = a.z - a.x;
        float ah = a.w - a.y;
        float ax = a.x + 0.5f * aw;
        float ay = a.y + 0.5f * ah;
        float cx = ax + r.x * 0.1f * aw;
        float cy = ay + r.y * 0.1f * ah;
        float w = aw * expf(r.z * 0.2f);
        float h = ah * expf(r.w * 0.2f);
        float x1 = fminf(fmaxf(cx - 0.5f * w, 0.0f), 640.0f);
        float y1 = fminf(fmaxf(cy - 0.5f * h, 0.0f), 640.0f);
        float x2 = fminf(fmaxf(cx + 0.5f * w, 0.0f), 640.0f);
        float y2 = fminf(fmaxf(cy + 0.5f * h, 0.0f), 640.0f);
        reinterpret_cast<float4*>(g_boxes)[gid] = make_float4(x1, y1, x2, y2);
        g_areas[gid] = (x2 - x1) * (y2 - y1);
    }

    // transpose one 32-anchor tile: cls[a0..a0+31][0..79] -> g_scoresT[c][a0..]
    int a0 = blockIdx.x * 32;
    if (a0 >= NA) return;
    if (a0 + 32 <= NA) {
        const float4* src = reinterpret_cast<const float4*>(cls + (size_t)a0 * 80);
        for (int idx = tid; idx < 640; idx += 256) {
            int ai = idx / 20, c4 = idx % 20;
            float4 v = src[ai * 20 + c4];
            tile[(c4 * 4 + 0) * 36 + ai] = v.x;
            tile[(c4 * 4 + 1) * 36 + ai] = v.y;
            tile[(c4 * 4 + 2) * 36 + ai] = v.z;
            tile[(c4 * 4 + 3) * 36 + ai] = v.w;
        }
        __syncthreads();
        for (int idx = tid; idx < 640; idx += 256) {
            int c = idx >> 3, j = idx & 7;
            float4 v = *reinterpret_cast<float4*>(&tile[c * 36 + 4 * j]);
            *reinterpret_cast<float4*>(&g_scoresT[(size_t)c * NA_R + a0 + 4 * j]) = v;
        }
    } else {
        for (int t2 = tid; t2 < 32 * 80; t2 += 256) {
            int ai = t2 / 80, cc = t2 % 80;
            if (a0 + ai < NA) tile[cc * 36 + ai] = cls[(size_t)(a0 + ai) * 80 + cc];
        }
        __syncthreads();
        for (int t2 = tid; t2 < 32 * 80; t2 += 256) {
            int cc = t2 >> 5, ai = t2 & 31;
            if (a0 + ai < NA) g_scoresT[(size_t)cc * NA_R + a0 + ai] = tile[cc * 36 + ai];
        }
    }
}

// ============ kernel 2: fill + per-class NMS + scatter ============
struct SmemT {
    float4 cbox[CAND];               // 32 KB
    unsigned long long keys[CAND];   // 16 KB
    float  carea[CAND];              // 8 KB
    float4 kbox[MAXK];
    float  karea[MAXK];
    float  kscore[MAXK];
    int    kidx[MAXK];
    unsigned mask[32];
    unsigned ph1bits;
    unsigned keepbits;
    int    cnt;
    int    kn_new;
    int    s_batch;
};

// queue-driven fill of output defaults; one fence per 512 KB batch
__device__ __forceinline__ void fill_defaults(float4* __restrict__ out4, SmemT& sm, int tid) {
    for (;;) {
        if (tid == 0) sm.s_batch = atomicAdd(&g_next, 1);
        __syncthreads();
        int b = sm.s_batch;
        if (b >= NBATCH) break;   // uniform exit, no further smem use
        int base = b * B4;
        bool uniform = (base + B4 <= N4) &&
                       !(base < LO4 && base + B4 > LO4) &&
                       !(base < HI4 && base + B4 > HI4);
        if (uniform) {
            float v = (base >= LO4 && base < HI4) ? -1.0f : 0.0f;
            float4 vv = make_float4(v, v, v, v);
            float4* p = out4 + base + tid;
#pragma unroll
            for (int it = 0; it < B4 / NT; it++) p[it * NT] = vv;
        } else {
            for (int it = 0; it < B4 / NT; it++) {
                int idx = base + it * NT + tid;
                if (idx < N4) {
                    float v = (idx >= LO4 && idx < HI4) ? -1.0f : 0.0f;
                    out4[idx] = make_float4(v, v, v, v);
                }
            }
        }
        __threadfence();      // release this batch's stores
        __syncthreads();      // all threads fenced; also guards s_batch reuse
        if (tid == 0) atomicAdd(&g_done, 1);
    }
}

__global__ void __launch_bounds__(NT, 2) k_main(float* __restrict__ out) {
    extern __shared__ char raw[];
    SmemT& sm = *reinterpret_cast<SmemT*>(raw);
    const int tid = threadIdx.x;
    const int wid = tid >> 5;
    const int lane = tid & 31;
    float4* out4 = reinterpret_cast<float4*>(out);

    if (blockIdx.x >= NC) {                 // helper CTA: fill only
        fill_defaults(out4, sm, tid);
        return;
    }

    const int c = blockIdx.x;
    const float* sc = g_scoresT + (size_t)c * NA_R;

    // ---- banded greedy NMS (descending-score bands, no count passes) ----
    float U = 1e30f;
    float t = 0.979f;
    int kn = 0;
    bool exhausted = false;
    bool lastBand = false;
    int tighten = 0;

    for (int band = 0; band < 256 && kn < MAXK; band++) {
        // selection scan with warp-aggregated compaction
        if (tid == 0) sm.cnt = 0;
        __syncthreads();
        for (int j = tid; j < NA_PAD; j += NT) {
            float s = (j < NA) ? __ldg(sc + j) : -1.0f;
            bool p = (s > t) && (s <= U);
            unsigned bal = __ballot_sync(FULLMASK, p);
            if (bal) {
                int base = 0;
                if (lane == 0) base = atomicAdd(&sm.cnt, __popc(bal));
                base = __shfl_sync(FULLMASK, base, 0);
                if (p) {
                    int pos2 = base + __popc(bal & ((1u << lane) - 1u));
                    if (pos2 < CAND) {
                        unsigned sb = ~__float_as_uint(s);
                        sm.keys[pos2] = ((unsigned long long)sb << 32) | (unsigned)j;
                    }
                }
            }
        }
        __syncthreads();
        int n_tr = sm.cnt;
        __syncthreads();                       // protect sm.cnt reuse

        if (n_tr > CAND && tighten < 24) {     // band too wide: tighten and rescan
            t = 0.5f * (t + fminf(U, 1.0f));
            lastBand = false;
            tighten++;
            continue;
        }
        tighten = 0;
        if (n_tr > CAND) n_tr = CAND;          // defensive clamp (statistically unreachable)

        int kn0_band = kn;
        if (n_tr > 0) {
            // bitonic sort, adaptive pow2 size (asc u64 = desc score, asc idx)
            int P = 32;
            while (P < n_tr) P <<= 1;
            for (int i = n_tr + tid; i < P; i += NT) sm.keys[i] = ~0ULL;
            __syncthreads();
            for (int k = 2; k <= P; k <<= 1) {
                for (int j2 = k >> 1; j2 > 0; j2 >>= 1) {
                    for (int i = tid; i < P; i += NT) {
                        int ixj = i ^ j2;
                        if (ixj > i) {
                            unsigned long long va = sm.keys[i];
                            unsigned long long vb = sm.keys[ixj];
                            bool up = ((i & k) == 0);
                            if ((va > vb) == up) { sm.keys[i] = vb; sm.keys[ixj] = va; }
                        }
                    }
                    __syncthreads();
                }
            }
            // gather candidate boxes/areas in sorted order
            for (int i = tid; i < n_tr; i += NT) {
                int idx = (int)(unsigned)(sm.keys[i] & 0xFFFFFFFFULL);
                sm.cbox[i] = reinterpret_cast<const float4*>(g_boxes)[idx];
                sm.carea[i] = g_areas[idx];
            }
            if (tid == 0) sm.ph1bits = 0;
            __syncthreads();

            // batched speculative greedy, 32 candidates/batch, 2 rows/warp
            int pos = 0;
            while (pos < n_tr && kn < MAXK) {
                int bn = n_tr - pos;
                if (bn > 32) bn = 32;
#pragma unroll
                for (int rr = 0; rr < 2; rr++) {
                    int r = wid + rr * 16;
                    // phase 1: row r vs confirmed kept list.
                    // Early-out loop: ALL lanes execute __any_sync every iteration
                    // (k-guard only on the load/compute) — convergence-safe.
                    bool sup = false;
                    if (r < bn) {
                        float4 cb = sm.cbox[pos + r];
                        float car = sm.carea[pos + r];
                        for (int k0 = 0; k0 < kn; k0 += 32) {
                            int k = k0 + lane;
                            if (k < kn) {
                                float4 kb = sm.kbox[k];
                                float ix1 = fmaxf(cb.x, kb.x);
                                float iy1 = fmaxf(cb.y, kb.y);
                                float ix2 = fminf(cb.z, kb.z);
                                float iy2 = fminf(cb.w, kb.w);
                                float inter = fmaxf(ix2 - ix1, 0.0f) * fmaxf(iy2 - iy1, 0.0f);
                                float iou = inter / (sm.karea[k] + car - inter);
                                if (iou > 0.5f) sup = true;
                            }
                            if (__any_sync(FULLMASK, sup)) break;
                        }
                    }
                    unsigned b = __ballot_sync(FULLMASK, sup);
                    if (lane == 0 && r < bn && b) atomicOr(&sm.ph1bits, 1u << r);
                    // phase 2: intra-batch pairwise matrix
                    bool hit = false;
                    if (r < bn && lane < bn && lane > r) {
                        float4 wb = sm.cbox[pos + r];
                        float4 jb = sm.cbox[pos + lane];
                        float ix1 = fmaxf(wb.x, jb.x);
                        float iy1 = fmaxf(wb.y, jb.y);
                        float ix2 = fminf(wb.z, jb.z);
                        float iy2 = fminf(wb.w, jb.w);
                        float inter = fmaxf(ix2 - ix1, 0.0f) * fmaxf(iy2 - iy1, 0.0f);
                        float iou = inter / (sm.carea[pos + r] + sm.carea[pos + lane] - inter);
                        hit = iou > 0.5f;
                    }
                    unsigned m = __ballot_sync(FULLMASK, hit);
                    if (lane == 0 && r < bn) sm.mask[r] = m;
                }
                __syncthreads();

                // serial order-exact resolve
                if (tid == 0) {
                    unsigned S = sm.ph1bits, keep = 0;
                    int knl = kn;
                    for (int i = 0; i < bn; i++) {
                        if (knl >= MAXK) break;
                        if (!((S >> i) & 1u)) {
                            keep |= 1u << i;
                            knl++;
                            S |= sm.mask[i];
                        }
                    }
                    sm.keepbits = keep;
                    sm.kn_new = knl;
                }
                __syncthreads();

                // record keeps; a non-warp-0 thread pre-clears ph1bits for next batch
                unsigned keep = sm.keepbits;
                if (tid < 32 && ((keep >> tid) & 1u)) {
                    int slot = kn + __popc(keep & ((1u << tid) - 1u));
                    unsigned long long key = sm.keys[pos + tid];
                    sm.kbox[slot] = sm.cbox[pos + tid];
                    sm.karea[slot] = sm.carea[pos + tid];
                    sm.kidx[slot] = (int)(unsigned)(key & 0xFFFFFFFFULL);
                    sm.kscore[slot] = __uint_as_float(~(unsigned)(key >> 32));
                }
                if (tid == 64) sm.ph1bits = 0;
                kn = sm.kn_new;
                __syncthreads();
                pos += 32;
            }
        }

        // advance band
        if (kn >= MAXK) break;
        if (lastBand) { exhausted = true; break; }
        U = t;
        float r = (float)(kn - kn0_band + 1) / (float)(n_tr + 1);
        float need = (float)(MAXK - kn) / r * 1.3f;
        float tstep = need / 76725.0f;
        tstep = fminf(tstep, 0.025f);
        tstep = fmaxf(tstep, 0.003f);
        t = U - tstep;
        if (t <= 0.1f) { t = 0.1f; lastBand = true; }
    }
    __syncthreads();

    // ---- help fill, then wait for all batches (bounded release/acquire spin) ----
    fill_defaults(out4, sm, tid);
    if (tid == 0) {
        for (long long spins = 0; spins < 500000; spins++) {
            if (atomicAdd(&g_done, 0) >= NBATCH) break;
            __nanosleep(100);
        }
        __threadfence();
    }
    __syncthreads();

    // ---- scatter kept detections ----
    // Reference quirk: pool exhausted before MAX_DET iterations forces keep[0]=False.
    for (int i = tid; i < kn; i += NT) {
        int a = sm.kidx[i];
        if (exhausted && a == 0) continue;
        size_t o = (size_t)c * NA + a;
        out[o] = sm.kscore[i];                                              // scores
        out[(size_t)CA + o] = (float)c;                                     // labels
        reinterpret_cast<float4*>(out + 2 * (size_t)CA)[o] = sm.kbox[i];    // boxes
        out[6 * (size_t)CA + o] = 1.0f;                                     // keep
    }
}

// ============ launcher ============
extern "C" void kernel_launch(void* const* d_in, const int* in_sizes, int n_in,
                              void* d_out, int out_size) {
    const float* cls = (const float*)d_in[0];     // [1, A, 80]
    const float4* reg = (const float4*)d_in[1];   // [1, A, 4]
    const float4* anc = (const float4*)d_in[2];   // [A, 4]
    float* out = (float*)d_out;

    cudaFuncSetAttribute(k_main, cudaFuncAttributeMaxDynamicSharedMemorySize,
                         (int)sizeof(SmemT));

    k_pre<<<NTILE, 256>>>(cls, reg, anc);
    k_main<<<GRID, NT, sizeof(SmemT)>>>(out);
}

// round 9
// speedup vs baseline: 1.8591x; 1.8591x over previous
#include <cuda_runtime.h>
#include <cstdint>

#define NA 76725
#define NA_R 76728               // padded row stride (multiple of 8) for float4 stores
#define NC 80
#define CA (NA * NC)             // 6,138,000
#define MAXK 200
#define CAND 2048
#define NT 1024
#define GRID 148
#define N4 ((7 * CA) / 4)        // 10,741,500 float4 in out buffer
#define B4 32768                 // float4 per fill batch (512 KB)
#define NBATCH ((N4 + B4 - 1) / B4)
#define LO4 (CA / 4)             // label region start (float4 units)
#define HI4 ((2 * CA) / 4)
#define FULLMASK 0xFFFFFFFFu
#define NTILE ((NA + 31) / 32)   // 2398
#define NA_PAD (((NA + NT - 1) / NT) * NT)

// -------- device scratch (no allocations allowed) --------
__device__ float g_boxes[NA * 4];
__device__ float g_areas[NA];
__device__ float g_scoresT[(size_t)NC * NA_R];
__device__ int g_next;
__device__ int g_done;

// IoU > 0.5 test, bit-identical decisions to reference's divide:
// cross-multiply fast path when outside a 1e-6 relative margin, exact divide inside.
__device__ __forceinline__ bool iou_gt_half(float4 a, float aa, float4 b, float ba) {
    float ix1 = fmaxf(a.x, b.x);
    float iy1 = fmaxf(a.y, b.y);
    float ix2 = fminf(a.z, b.z);
    float iy2 = fminf(a.w, b.w);
    float inter = fmaxf(ix2 - ix1, 0.0f) * fmaxf(iy2 - iy1, 0.0f);
    float d = aa + ba - inter;                 // always >= 0 (inter <= min(aa,ba))
    float tt = fmaf(-0.5f, d, inter);          // inter - 0.5*d
    if (fabsf(tt) > 1e-6f * d) return tt > 0.0f;
    return (inter / d) > 0.5f;                 // rare exact fallback (handles d==0 too)
}

// ============ kernel 1: reset counters + decode + transpose ============
__global__ void __launch_bounds__(256) k_pre(const float* __restrict__ cls,
                                             const float4* __restrict__ reg,
                                             const float4* __restrict__ anc) {
    __shared__ float tile[80 * 36];
    const int tid = threadIdx.x;
    if (blockIdx.x == 0 && tid == 0) { g_next = 0; g_done = 0; }

    int gid = blockIdx.x * 256 + tid;
    if (gid < NA) {
        float4 a = anc[gid];
        float4 r = reg[gid];
        float aw = a.z - a.x;
        float ah = a.w - a.y;
        float ax = a.x + 0.5f * aw;
        float ay = a.y + 0.5f * ah;
        float cx = ax + r.x * 0.1f * aw;
        float cy = ay + r.y * 0.1f * ah;
        float w = aw * expf(r.z * 0.2f);
        float h = ah * expf(r.w * 0.2f);
        float x1 = fminf(fmaxf(cx - 0.5f * w, 0.0f), 640.0f);
        float y1 = fminf(fmaxf(cy - 0.5f * h, 0.0f), 640.0f);
        float x2 = fminf(fmaxf(cx + 0.5f * w, 0.0f), 640.0f);
        float y2 = fminf(fmaxf(cy + 0.5f * h, 0.0f), 640.0f);
        reinterpret_cast<float4*>(g_boxes)[gid] = make_float4(x1, y1, x2, y2);
        g_areas[gid] = (x2 - x1) * (y2 - y1);
    }

    int a0 = blockIdx.x * 32;
    if (a0 >= NA) return;
    if (a0 + 32 <= NA) {
        const float4* src = reinterpret_cast<const float4*>(cls + (size_t)a0 * 80);
        for (int idx = tid; idx < 640; idx += 256) {
            int ai = idx / 20, c4 = idx % 20;
            float4 v = src[ai * 20 + c4];
            tile[(c4 * 4 + 0) * 36 + ai] = v.x;
            tile[(c4 * 4 + 1) * 36 + ai] = v.y;
            tile[(c4 * 4 + 2) * 36 + ai] = v.z;
            tile[(c4 * 4 + 3) * 36 + ai] = v.w;
        }
        __syncthreads();
        for (int idx = tid; idx < 640; idx += 256) {
            int c = idx >> 3, j = idx & 7;
            float4 v = *reinterpret_cast<float4*>(&tile[c * 36 + 4 * j]);
            *reinterpret_cast<float4*>(&g_scoresT[(size_t)c * NA_R + a0 + 4 * j]) = v;
        }
    } else {
        for (int t2 = tid; t2 < 32 * 80; t2 += 256) {
            int ai = t2 / 80, cc = t2 % 80;
            if (a0 + ai < NA) tile[cc * 36 + ai] = cls[(size_t)(a0 + ai) * 80 + cc];
        }
        __syncthreads();
        for (int t2 = tid; t2 < 32 * 80; t2 += 256) {
            int cc = t2 >> 5, ai = t2 & 31;
            if (a0 + ai < NA) g_scoresT[(size_t)cc * NA_R + a0 + ai] = tile[cc * 36 + ai];
        }
    }
}

// ============ kernel 2: fill + per-class NMS + scatter ============
struct SmemT {
    float4 cbox[CAND];               // 32 KB
    unsigned long long keys[CAND];   // 16 KB
    float  carea[CAND];              // 8 KB
    float4 kbox[MAXK];
    float  karea[MAXK];
    float  kscore[MAXK];
    int    kidx[MAXK];
    unsigned mask[32];
    unsigned ph1bits;
    unsigned keepbits;
    int    cnt;
    int    kn_new;
    int    s_batch;
};

__device__ __forceinline__ void fill_defaults(float4* __restrict__ out4, SmemT& sm, int tid) {
    for (;;) {
        if (tid == 0) sm.s_batch = atomicAdd(&g_next, 1);
        __syncthreads();
        int b = sm.s_batch;
        if (b >= NBATCH) break;
        int base = b * B4;
        bool uniform = (base + B4 <= N4) &&
                       !(base < LO4 && base + B4 > LO4) &&
                       !(base < HI4 && base + B4 > HI4);
        if (uniform) {
            float v = (base >= LO4 && base < HI4) ? -1.0f : 0.0f;
            float4 vv = make_float4(v, v, v, v);
            float4* p = out4 + base + tid;
#pragma unroll
            for (int it = 0; it < B4 / NT; it++) p[it * NT] = vv;
        } else {
            for (int it = 0; it < B4 / NT; it++) {
                int idx = base + it * NT + tid;
                if (idx < N4) {
                    float v = (idx >= LO4 && idx < HI4) ? -1.0f : 0.0f;
                    out4[idx] = make_float4(v, v, v, v);
                }
            }
        }
        __threadfence();
        __syncthreads();
        if (tid == 0) atomicAdd(&g_done, 1);
    }
}

__global__ void __launch_bounds__(NT, 1) k_main(float* __restrict__ out) {
    extern __shared__ char raw[];
    SmemT& sm = *reinterpret_cast<SmemT*>(raw);
    const int tid = threadIdx.x;
    const int wid = tid >> 5;
    const int lane = tid & 31;
    float4* out4 = reinterpret_cast<float4*>(out);

    if (blockIdx.x >= NC) {                 // helper CTA: fill only
        fill_defaults(out4, sm, tid);
        return;
    }

    const int c = blockIdx.x;
    const float* sc = g_scoresT + (size_t)c * NA_R;

    // ---- banded greedy NMS ----
    float U = 1e30f;
    float t = 0.979f;
    int kn = 0;
    bool exhausted = false;
    bool lastBand = false;
    int tighten = 0;

    for (int band = 0; band < 256 && kn < MAXK; band++) {
        // selection scan, warp-aggregated compaction
        if (tid == 0) sm.cnt = 0;
        __syncthreads();
        for (int j = tid; j < NA_PAD; j += NT) {
            float s = (j < NA) ? __ldg(sc + j) : -1.0f;
            bool p = (s > t) && (s <= U);
            unsigned bal = __ballot_sync(FULLMASK, p);
            if (bal) {
                int base = 0;
                if (lane == 0) base = atomicAdd(&sm.cnt, __popc(bal));
                base = __shfl_sync(FULLMASK, base, 0);
                if (p) {
                    int pos2 = base + __popc(bal & ((1u << lane) - 1u));
                    if (pos2 < CAND) {
                        unsigned sb = ~__float_as_uint(s);
                        sm.keys[pos2] = ((unsigned long long)sb << 32) | (unsigned)j;
                    }
                }
            }
        }
        __syncthreads();
        int n_tr = sm.cnt;
        __syncthreads();

        if (n_tr > CAND && tighten < 24) {     // band too wide: tighten and rescan
            t = 0.5f * (t + fminf(U, 1.0f));
            lastBand = false;
            tighten++;
            continue;
        }
        tighten = 0;
        if (n_tr > CAND) n_tr = CAND;

        int kn0_band = kn;
        if (n_tr > 0) {
            // bitonic sort, adaptive pow2 size (asc u64 = desc score, asc idx)
            int P = 32;
            while (P < n_tr) P <<= 1;
            for (int i = n_tr + tid; i < P; i += NT) sm.keys[i] = ~0ULL;
            __syncthreads();
            for (int k = 2; k <= P; k <<= 1) {
                for (int j2 = k >> 1; j2 > 0; j2 >>= 1) {
                    for (int i = tid; i < P; i += NT) {
                        int ixj = i ^ j2;
                        if (ixj > i) {
                            unsigned long long va = sm.keys[i];
                            unsigned long long vb = sm.keys[ixj];
                            bool up = ((i & k) == 0);
                            if ((va > vb) == up) { sm.keys[i] = vb; sm.keys[ixj] = va; }
                        }
                    }
                    __syncthreads();
                }
            }
            // gather candidate boxes/areas in sorted order
            for (int i = tid; i < n_tr; i += NT) {
                int idx = (int)(unsigned)(sm.keys[i] & 0xFFFFFFFFULL);
                sm.cbox[i] = reinterpret_cast<const float4*>(g_boxes)[idx];
                sm.carea[i] = g_areas[idx];
            }
            if (tid == 0) sm.ph1bits = 0;
            __syncthreads();

            // batched speculative greedy: 32 candidates/batch, 1 row/warp
            int pos = 0;
            while (pos < n_tr && kn < MAXK) {
                int bn = n_tr - pos;
                if (bn > 32) bn = 32;
                int r = wid;   // 32 warps -> 32 rows

                // phase 1: row r vs confirmed kept list (convergence-safe early-out)
                bool sup = false;
                if (r < bn) {
                    float4 cb = sm.cbox[pos + r];
                    float car = sm.carea[pos + r];
                    for (int k0 = 0; k0 < kn; k0 += 32) {
                        int k = k0 + lane;
                        if (k < kn && iou_gt_half(cb, car, sm.kbox[k], sm.karea[k]))
                            sup = true;
                        if (__any_sync(FULLMASK, sup)) break;
                    }
                }
                unsigned b = __ballot_sync(FULLMASK, sup);
                if (lane == 0 && r < bn && b) atomicOr(&sm.ph1bits, 1u << r);

                // phase 2: intra-batch pairwise matrix (row r vs later cols)
                bool hit = false;
                if (r < bn && lane < bn && lane > r) {
                    hit = iou_gt_half(sm.cbox[pos + r], sm.carea[pos + r],
                                      sm.cbox[pos + lane], sm.carea[pos + lane]);
                }
                unsigned m = __ballot_sync(FULLMASK, hit);
                if (lane == 0 && r < bn) sm.mask[r] = m;
                __syncthreads();

                // serial order-exact resolve
                if (tid == 0) {
                    unsigned S = sm.ph1bits, keep = 0;
                    int knl = kn;
                    for (int i = 0; i < bn; i++) {
                        if (knl >= MAXK) break;
                        if (!((S >> i) & 1u)) {
                            keep |= 1u << i;
                            knl++;
                            S |= sm.mask[i];
                        }
                    }
                    sm.keepbits = keep;
                    sm.kn_new = knl;
                }
                __syncthreads();

                // record keeps; a non-warp-0 thread pre-clears ph1bits for next batch
                unsigned keep = sm.keepbits;
                if (tid < 32 && ((keep >> tid) & 1u)) {
                    int slot = kn + __popc(keep & ((1u << tid) - 1u));
                    unsigned long long key = sm.keys[pos + tid];
                    sm.kbox[slot] = sm.cbox[pos + tid];
                    sm.karea[slot] = sm.carea[pos + tid];
                    sm.kidx[slot] = (int)(unsigned)(key & 0xFFFFFFFFULL);
                    sm.kscore[slot] = __uint_as_float(~(unsigned)(key >> 32));
                }
                if (tid == 64) sm.ph1bits = 0;
                kn = sm.kn_new;
                __syncthreads();
                pos += 32;
            }
        }

        // advance band
        if (kn >= MAXK) break;
        if (lastBand) { exhausted = true; break; }
        U = t;
        float r = (float)(kn - kn0_band + 1) / (float)(n_tr + 1);
        float need = (float)(MAXK - kn) / r * 1.3f;
        float tstep = need / 76725.0f;
        tstep = fminf(tstep, 0.025f);
        tstep = fmaxf(tstep, 0.003f);
        t = U - tstep;
        if (t <= 0.1f) { t = 0.1f; lastBand = true; }
    }
    __syncthreads();

    // ---- help fill, then wait for all batches (bounded spin) ----
    fill_defaults(out4, sm, tid);
    if (tid == 0) {
        for (long long spins = 0; spins < 500000; spins++) {
            if (atomicAdd(&g_done, 0) >= NBATCH) break;
            __nanosleep(100);
        }
        __threadfence();
    }
    __syncthreads();

    // ---- scatter kept detections ----
    // Reference quirk: pool exhausted before MAX_DET iterations forces keep[0]=False.
    for (int i = tid; i < kn; i += NT) {
        int a = sm.kidx[i];
        if (exhausted && a == 0) continue;
        size_t o = (size_t)c * NA + a;
        out[o] = sm.kscore[i];                                              // scores
        out[(size_t)CA + o] = (float)c;                                     // labels
        reinterpret_cast<float4*>(out + 2 * (size_t)CA)[o] = sm.kbox[i];    // boxes
        out[6 * (size_t)CA + o] = 1.0f;                                     // keep
    }
}

// ============ launcher ============
extern "C" void kernel_launch(void* const* d_in, const int* in_sizes, int n_in,
                              void* d_out, int out_size) {
    const float* cls = (const float*)d_in[0];     // [1, A, 80]
    const float4* reg = (const float4*)d_in[1];   // [1, A, 4]
    const float4* anc = (const float4*)d_in[2];   // [A, 4]
    float* out = (float*)d_out;

    cudaFuncSetAttribute(k_main, cudaFuncAttributeMaxDynamicSharedMemorySize,
                         (int)sizeof(SmemT));

    k_pre<<<NTILE, 256>>>(cls, reg, anc);
    k_main<<<GRID, NT, sizeof(SmemT)>>>(out);
}